// round 6
// baseline (speedup 1.0000x reference)
#include <cuda_runtime.h>

#define NB 32
#define TT 16384
#define HH 64
#define WT 128         // worker threads (4 warps)
#define BT 160         // + 1 head/store warp
#define XCHUNK 64

typedef unsigned long long ull;

// ---- packed f32x2 helpers (Blackwell; only reachable via PTX) ----
__device__ __forceinline__ ull fma2(ull a, ull b, ull c) {
    ull d;
    asm("fma.rn.f32x2 %0, %1, %2, %3;" : "=l"(d) : "l"(a), "l"(b), "l"(c));
    return d;
}
__device__ __forceinline__ ull add2(ull a, ull b) {
    ull d;
    asm("add.rn.f32x2 %0, %1, %2;" : "=l"(d) : "l"(a), "l"(b));
    return d;
}
__device__ __forceinline__ void unpack2(ull v, float& lo, float& hi) {
    asm("mov.b64 {%0, %1}, %2;" : "=f"(lo), "=f"(hi) : "l"(v));
}
__device__ __forceinline__ ull pack2(float lo, float hi) {
    ull v;
    asm("mov.b64 %0, {%1, %2};" : "=l"(v) : "f"(lo), "f"(hi));
    return v;
}

// MUFU.TANH-based nonlinearities (lat 16 vs ~40-48 for the EX2+RCP chains)
__device__ __forceinline__ float tanh_a(float v) {
    float r;
    asm("tanh.approx.f32 %0, %1;" : "=f"(r) : "f"(v));
    return r;
}
__device__ __forceinline__ float sig_a(float v) {
    return fmaf(0.5f, tanh_a(0.5f * v), 0.5f);
}

// explicit full-block named barrier (legal from divergent call sites; counts
// to BT arrivals). memory clobber orders smem across it.
#define BAR_ALL() asm volatile("bar.sync 0, %0;" :: "r"(BT) : "memory")

// 32-element half-dot: 16 packed fma2 over register-resident w and h.
__device__ __forceinline__ float dot16(const ull* w, const ull* hv, float bias) {
    ull a0 = pack2(bias, 0.0f), a1 = 0ull, a2 = 0ull, a3 = 0ull;
    #pragma unroll
    for (int j = 0; j < 16; j += 4) {
        a0 = fma2(w[j],     hv[j],     a0);
        a1 = fma2(w[j + 1], hv[j + 1], a1);
        a2 = fma2(w[j + 2], hv[j + 2], a2);
        a3 = fma2(w[j + 3], hv[j + 3], a3);
    }
    float lo, hi;
    unpack2(add2(add2(a0, a1), add2(a2, a3)), lo, hi);
    return lo + hi;
}

// ---------------------------------------------------------------------------
// Fully fused GRU scan + linear head. One block per batch, 5 warps:
//   warps 0-3 (128 thr): lane pair (even,odd) owns h-index p = w*16 + l/2.
//     Each thread computes the 32-column half-dot of ALL THREE gate rows for
//     p; halves combine with one shfl.bfly per gate (intra-warp). Even lane
//     runs the nonlinear tail and writes h. ONE barrier per step.
//   warp 4 (32 thr): after each barrier reads h(t), stores states[b,t,:] and
//     computes out[b,t] (shfl reduce) — fully shadowed by the next dot phase.
// ---------------------------------------------------------------------------
__global__ void __launch_bounds__(BT, 1) gru_fused_kernel(
    const float* __restrict__ x,
    const float* __restrict__ W_ih,
    const float* __restrict__ W_hh,
    const float* __restrict__ b_ih,
    const float* __restrict__ b_hh,
    const float* __restrict__ W_out,
    const float* __restrict__ b_out,
    float* __restrict__ out,
    float* __restrict__ states)
{
    const int b = blockIdx.x;
    const int tid = threadIdx.x;

    __shared__ float h_sh[2][HH];        // double-buffered hidden state
    __shared__ float x_sh[2][XCHUNK];    // x prefetch chunks

    const float* xb = x + (size_t)b * TT;

    if (tid < HH) {
        h_sh[0][tid] = 0.0f;
        x_sh[0][tid] = xb[tid];
    }
    BAR_ALL();

    if (tid < WT) {
        // ----------------------- worker warps -----------------------
        const int l = tid & 31;
        const int p = (tid >> 5) * 16 + (l >> 1);   // h-index owned
        const int half = l & 1;                      // 0: cols 0-31, 1: 32-63
        const int colbase = half << 5;

        // Register-resident half-rows of W_hh for gates r,z,n (row stride 64).
        ull wr[16], wz[16], wn[16];
        {
            const ulonglong2* sr = (const ulonglong2*)(W_hh + (size_t)p * HH + colbase);
            const ulonglong2* sz = (const ulonglong2*)(W_hh + (size_t)(HH + p) * HH + colbase);
            const ulonglong2* sn = (const ulonglong2*)(W_hh + (size_t)(2 * HH + p) * HH + colbase);
            #pragma unroll
            for (int j = 0; j < 8; j++) {
                ulonglong2 vr = sr[j]; wr[2 * j] = vr.x; wr[2 * j + 1] = vr.y;
                ulonglong2 vz = sz[j]; wz[2 * j] = vz.x; wz[2 * j + 1] = vz.y;
                ulonglong2 vn = sn[j]; wn[2 * j] = vn.x; wn[2 * j + 1] = vn.y;
            }
        }
        // b_hh folded into even lane's accumulator init (counted once).
        const float br = half ? 0.0f : b_hh[p];
        const float bz = half ? 0.0f : b_hh[HH + p];
        const float bn = half ? 0.0f : b_hh[2 * HH + p];
        // input projection constants (used by even lane only)
        const float wir = W_ih[p],          bir = b_ih[p];
        const float wiz = W_ih[HH + p],     biz = b_ih[HH + p];
        const float win = W_ih[2 * HH + p], bin = b_ih[2 * HH + p];

        float h = 0.0f, xnext = 0.0f;
        int tmod = 0, buf = 0, cur = 0;

        for (int t = 0; t < TT; t++) {
            // x double-buffer (even lanes): LDG at chunk start, commit mid-chunk
            if (half == 0) {
                if (tmod == 0) {
                    int tn = t + XCHUNK;
                    if (tn < TT) xnext = xb[tn + p];
                } else if (tmod == XCHUNK / 2) {
                    if (t + XCHUNK / 2 < TT) x_sh[buf ^ 1][p] = xnext;
                }
            }

            // Load own 32-col half of h into regs (8 LDS.128, 2-way bcast).
            ull hv[16];
            {
                const ulonglong2* hp = (const ulonglong2*)&h_sh[cur][colbase];
                #pragma unroll
                for (int j = 0; j < 8; j++) {
                    ulonglong2 v = hp[j];
                    hv[2 * j] = v.x; hv[2 * j + 1] = v.y;
                }
            }
            float sr = dot16(wr, hv, br);
            float sz = dot16(wz, hv, bz);
            float sn = dot16(wn, hv, bn);
            // combine halves: one shfl per gate, intra-warp, no barrier
            sr += __shfl_xor_sync(0xffffffffu, sr, 1);
            sz += __shfl_xor_sync(0xffffffffu, sz, 1);
            sn += __shfl_xor_sync(0xffffffffu, sn, 1);

            if (half == 0) {
                const float xt = x_sh[buf][tmod];
                const float r = sig_a(fmaf(xt, wir, bir) + sr);
                const float z = sig_a(fmaf(xt, wiz, biz) + sz);
                const float n = tanh_a(fmaf(r, sn, fmaf(xt, win, bin)));
                h = n + z * (h - n);             // (1-z)*n + z*h
                h_sh[cur ^ 1][p] = h;
            }
            BAR_ALL();
            cur ^= 1;
            if (++tmod == XCHUNK) { tmod = 0; buf ^= 1; }
        }
    } else {
        // ----------------------- head/store warp -----------------------
        const int l = tid - WT;                      // 0..31
        const float w0 = W_out[l];
        const float w1 = W_out[32 + l];
        const float bo = b_out[0];
        float* st = states + (size_t)b * TT * HH;
        float* ob = out + (size_t)b * TT;
        int tmod = 0, buf = 0, cur = 0;

        for (int t = 0; t < TT; t++) {
            BAR_ALL();
            cur ^= 1;                                // h(t) now in h_sh[cur]
            const float h0 = h_sh[cur][l];
            const float h1 = h_sh[cur][32 + l];
            st[(size_t)t * HH + l]      = h0;        // states store (coalesced)
            st[(size_t)t * HH + 32 + l] = h1;
            float ps = fmaf(h0, w0, h1 * w1);
            #pragma unroll
            for (int o = 16; o > 0; o >>= 1)
                ps += __shfl_xor_sync(0xffffffffu, ps, o);
            if (l == 0) ob[t] = ps + bo + x_sh[buf][tmod];
            if (++tmod == XCHUNK) { tmod = 0; buf ^= 1; }
        }
    }
}

extern "C" void kernel_launch(void* const* d_in, const int* in_sizes, int n_in,
                              void* d_out, int out_size) {
    const float* x     = (const float*)d_in[0];
    const float* W_ih  = (const float*)d_in[1];
    const float* W_hh  = (const float*)d_in[2];
    const float* b_ih  = (const float*)d_in[3];
    const float* b_hh  = (const float*)d_in[4];
    const float* W_out = (const float*)d_in[5];
    const float* b_out = (const float*)d_in[6];

    float* out    = (float*)d_out;              // [B*T]   (tuple elem 0)
    float* states = out + (size_t)NB * TT;      // [B*T*H] (tuple elem 1)

    gru_fused_kernel<<<NB, BT>>>(x, W_ih, W_hh, b_ih, b_hh, W_out, b_out,
                                 out, states);
}